// round 1
// baseline (speedup 1.0000x reference)
#include <cuda_runtime.h>
#include <cstdint>
#include <math.h>

// ---------------------------------------------------------------------------
// Problem constants
// ---------------------------------------------------------------------------
#define BS   2
#define NQ   16384
#define E    256
#define NH   8
#define NL   4
#define NP   4
#define DH   32            // E / NH
#define TOTV 21760         // total spatial positions across levels
#define NOUT 384           // 256 offsets + 128 attn logits per query
#define M_TOT (BS * NQ)    // 32768

// Level starts: 0, 16384, 20480, 21504  (128^2, 64^2, 32^2, 16^2)

// Scratch for GEMM output: [32768, 384] f32 = 50.3 MB
__device__ float g_scratch[(size_t)M_TOT * NOUT];

// ---------------------------------------------------------------------------
// tf32 helpers
// ---------------------------------------------------------------------------
__device__ __forceinline__ unsigned f2tf(float x) {
    unsigned r;
    asm("cvt.rna.tf32.f32 %0, %1;" : "=r"(r) : "f"(x));
    return r;
}

__device__ __forceinline__ void mma_tf32(float c[4], const unsigned a[4],
                                         unsigned b0, unsigned b1) {
    asm volatile(
        "mma.sync.aligned.m16n8k8.row.col.f32.tf32.tf32.f32 "
        "{%0,%1,%2,%3}, {%4,%5,%6,%7}, {%8,%9}, {%0,%1,%2,%3};"
        : "+f"(c[0]), "+f"(c[1]), "+f"(c[2]), "+f"(c[3])
        : "r"(a[0]), "r"(a[1]), "r"(a[2]), "r"(a[3]), "r"(b0), "r"(b1));
}

// ---------------------------------------------------------------------------
// GEMM: C[m, n] = sum_k Q[m,k] * Wc[n,k] + bias[n]
//   m in [0, 32768), n in [0, 384), k in [0, 256)
//   Wc rows 0..255 = W_off, rows 256..383 = W_attn
// Block tile: BM=128, BN=64, BK=32.  256 threads = 8 warps, warp tile 32x32.
// ---------------------------------------------------------------------------
__global__ __launch_bounds__(256) void gemm_kernel(
    const float* __restrict__ Q,
    const float* __restrict__ Woff,
    const float* __restrict__ Wattn,
    const float* __restrict__ boff,
    const float* __restrict__ battn)
{
    __shared__ unsigned As[128][33];
    __shared__ unsigned Bs[64][33];

    const int tid  = threadIdx.x;
    const int m0   = blockIdx.x * 128;
    const int n0   = blockIdx.y * 64;
    const int warp = tid >> 5, lane = tid & 31;
    const int wm   = (warp & 3) * 32;   // warp row in tile
    const int wn   = (warp >> 2) * 32;  // warp col in tile
    const int g    = lane >> 2;         // groupID 0..7
    const int tg   = lane & 3;          // thread in group 0..3

    float acc[2][4][4];
#pragma unroll
    for (int mi = 0; mi < 2; mi++)
#pragma unroll
        for (int ni = 0; ni < 4; ni++)
#pragma unroll
            for (int k = 0; k < 4; k++) acc[mi][ni][k] = 0.f;

    for (int kt = 0; kt < 256; kt += 32) {
        // Stage A tile: 128x32
#pragma unroll
        for (int i = 0; i < 4; i++) {
            int idx = tid + i * 256;            // 0..1023 float4 slots
            int r = idx >> 3, cc = (idx & 7) * 4;
            float4 v = *(const float4*)(Q + (size_t)(m0 + r) * 256 + kt + cc);
            As[r][cc + 0] = f2tf(v.x);
            As[r][cc + 1] = f2tf(v.y);
            As[r][cc + 2] = f2tf(v.z);
            As[r][cc + 3] = f2tf(v.w);
        }
        // Stage B tile: 64x32
#pragma unroll
        for (int i = 0; i < 2; i++) {
            int idx = tid + i * 256;            // 0..511
            int r = idx >> 3, cc = (idx & 7) * 4;
            int n = n0 + r;
            const float* src = (n < 256) ? (Woff + (size_t)n * 256)
                                         : (Wattn + (size_t)(n - 256) * 256);
            float4 v = *(const float4*)(src + kt + cc);
            Bs[r][cc + 0] = f2tf(v.x);
            Bs[r][cc + 1] = f2tf(v.y);
            Bs[r][cc + 2] = f2tf(v.z);
            Bs[r][cc + 3] = f2tf(v.w);
        }
        __syncthreads();

#pragma unroll
        for (int kk = 0; kk < 32; kk += 8) {
            unsigned a[2][4];
#pragma unroll
            for (int mi = 0; mi < 2; mi++) {
                int r = wm + mi * 16 + g;
                a[mi][0] = As[r][kk + tg];
                a[mi][1] = As[r + 8][kk + tg];
                a[mi][2] = As[r][kk + tg + 4];
                a[mi][3] = As[r + 8][kk + tg + 4];
            }
#pragma unroll
            for (int ni = 0; ni < 4; ni++) {
                unsigned b0 = Bs[wn + ni * 8 + g][kk + tg];
                unsigned b1 = Bs[wn + ni * 8 + g][kk + tg + 4];
                mma_tf32(acc[0][ni], a[0], b0, b1);
                mma_tf32(acc[1][ni], a[1], b0, b1);
            }
        }
        __syncthreads();
    }

    // Epilogue: add bias, write to scratch
#pragma unroll
    for (int mi = 0; mi < 2; mi++) {
        int row = m0 + wm + mi * 16 + g;
#pragma unroll
        for (int ni = 0; ni < 4; ni++) {
            int col = n0 + wn + ni * 8 + 2 * tg;
            float b0v = (col < 256) ? boff[col] : battn[col - 256];
            float b1v = (col + 1 < 256) ? boff[col + 1] : battn[col + 1 - 256];
            g_scratch[(size_t)row * NOUT + col]           = acc[mi][ni][0] + b0v;
            g_scratch[(size_t)row * NOUT + col + 1]       = acc[mi][ni][1] + b1v;
            g_scratch[(size_t)(row + 8) * NOUT + col]     = acc[mi][ni][2] + b0v;
            g_scratch[(size_t)(row + 8) * NOUT + col + 1] = acc[mi][ni][3] + b1v;
        }
    }
}

// ---------------------------------------------------------------------------
// MSDA kernel: softmax + 16-point bilinear gather + weighted sum.
// Block = 1024 threads = 32 warps; one block handles (b, h, 32 queries).
// Warp = one query; lane = channel c (0..31).
// grid = (512, 8, 2) -> (q-block, h, b)
// ---------------------------------------------------------------------------
__global__ __launch_bounds__(1024) void msda_kernel(
    const float* __restrict__ value,
    const float* __restrict__ refp,
    float* __restrict__ out)
{
    const int b    = blockIdx.z;
    const int h    = blockIdx.y;
    const int warp = threadIdx.x >> 5;
    const int lane = threadIdx.x & 31;
    const int q    = blockIdx.x * 32 + warp;
    const int qg   = b * NQ + q;

    const float* sc = g_scratch + (size_t)qg * NOUT;

    // ---- softmax over 16 logits (lanes 0..15 hold one logit each) ----
    float lg = (lane < 16) ? sc[256 + h * 16 + lane] : -1e30f;
    float mx = lg;
#pragma unroll
    for (int o = 16; o > 0; o >>= 1)
        mx = fmaxf(mx, __shfl_xor_sync(0xffffffffu, mx, o));
    float e = (lane < 16) ? __expf(lg - mx) : 0.f;
    float s = e;
#pragma unroll
    for (int o = 16; o > 0; o >>= 1)
        s += __shfl_xor_sync(0xffffffffu, s, o);
    float w = e / s;

    // ---- per-lane staging of offsets / ref points ----
    float ofv = sc[h * 32 + lane];                           // (l*8 + p*2 + xy)
    float rv  = (lane < 8) ? refp[(size_t)qg * 8 + lane] : 0.f;

    float acc = 0.f;
    const float* vb0 = value + (size_t)b * TOTV * 256 + h * 32 + lane;

#pragma unroll
    for (int l = 0; l < 4; l++) {
        const int Wl = 128 >> l;
        const int Hl = 128 >> l;
        const int start = (l == 0) ? 0 : (l == 1) ? 16384 : (l == 2) ? 20480 : 21504;
        const float* vb = vb0 + (size_t)start * 256;
#pragma unroll
        for (int p = 0; p < 4; p++) {
            const int i = l * 4 + p;
            float ox = __shfl_sync(0xffffffffu, ofv, 2 * i);
            float oy = __shfl_sync(0xffffffffu, ofv, 2 * i + 1);
            float rx = __shfl_sync(0xffffffffu, rv, 2 * p);
            float ry = __shfl_sync(0xffffffffu, rv, 2 * p + 1);
            float wt = __shfl_sync(0xffffffffu, w, i);

            float x = rx * (float)Wl + ox - 0.5f;
            float y = ry * (float)Hl + oy - 0.5f;
            float xf = floorf(x), yf = floorf(y);
            int ix = (int)xf, iy = (int)yf;
            float fx = x - xf, fy = y - yf;

            bool vx0 = (unsigned)ix       < (unsigned)Wl;
            bool vx1 = (unsigned)(ix + 1) < (unsigned)Wl;
            bool vy0 = (unsigned)iy       < (unsigned)Hl;
            bool vy1 = (unsigned)(iy + 1) < (unsigned)Hl;

            int off00 = (iy * Wl + ix) * 256;   // fits int32 even when negative
            float v00 = (vx0 && vy0) ? __ldg(vb + off00)            : 0.f;
            float v01 = (vx1 && vy0) ? __ldg(vb + off00 + 256)      : 0.f;
            float v10 = (vx0 && vy1) ? __ldg(vb + off00 + Wl * 256) : 0.f;
            float v11 = (vx1 && vy1) ? __ldg(vb + off00 + Wl * 256 + 256) : 0.f;

            float a0 = v00 + fx * (v01 - v00);
            float a1 = v10 + fx * (v11 - v10);
            acc += wt * (a0 + fy * (a1 - a0));
        }
    }

    // ---- smem transpose so output writes are coalesced along q ----
    __shared__ float sm[32][33];
    sm[lane][warp] = acc;            // sm[channel][q_local]
    __syncthreads();
    // warp = channel row, lane = q offset -> 128B coalesced store
    out[((size_t)(b * 256 + h * 32 + warp)) * NQ + blockIdx.x * 32 + lane] =
        sm[warp][lane];
}

// ---------------------------------------------------------------------------
// Launch
// ---------------------------------------------------------------------------
extern "C" void kernel_launch(void* const* d_in, const int* in_sizes, int n_in,
                              void* d_out, int out_size) {
    const float* query = (const float*)d_in[0];
    const float* value = (const float*)d_in[1];
    const float* refp  = (const float*)d_in[2];
    const float* Woff  = (const float*)d_in[3];
    const float* boff  = (const float*)d_in[4];
    const float* Wattn = (const float*)d_in[5];
    const float* battn = (const float*)d_in[6];
    float* out = (float*)d_out;

    dim3 ggrid(M_TOT / 128, NOUT / 64);          // (256, 6)
    gemm_kernel<<<ggrid, 256>>>(query, Woff, Wattn, boff, battn);

    dim3 mgrid(NQ / 32, NH, BS);                 // (512, 8, 2)
    msda_kernel<<<mgrid, 1024>>>(value, refp, out);
}

// round 2
// speedup vs baseline: 1.5591x; 1.5591x over previous
#include <cuda_runtime.h>
#include <cstdint>
#include <math.h>

// ---------------------------------------------------------------------------
// Problem constants
// ---------------------------------------------------------------------------
#define BS   2
#define NQ   16384
#define E    256
#define NH   8
#define NL   4
#define NP   4
#define TOTV 21760         // total spatial positions across levels
#define NOUT 384           // 256 offsets + 128 attn logits per query
#define M_TOT (BS * NQ)    // 32768

// Scratch for GEMM output: [32768, 384] f32
__device__ float g_scratch[(size_t)M_TOT * NOUT];

// ---------------------------------------------------------------------------
// tf32 mma (operands are raw fp32 bits -> hardware truncates to tf32)
// ---------------------------------------------------------------------------
__device__ __forceinline__ void mma_tf32(float c[4], const unsigned a[4],
                                         unsigned b0, unsigned b1) {
    asm volatile(
        "mma.sync.aligned.m16n8k8.row.col.f32.tf32.tf32.f32 "
        "{%0,%1,%2,%3}, {%4,%5,%6,%7}, {%8,%9}, {%0,%1,%2,%3};"
        : "+f"(c[0]), "+f"(c[1]), "+f"(c[2]), "+f"(c[3])
        : "r"(a[0]), "r"(a[1]), "r"(a[2]), "r"(a[3]), "r"(b0), "r"(b1));
}

// ---------------------------------------------------------------------------
// GEMM: C[m,n] = sum_k Q[m,k] * Wc[n,k] + bias[n]
//   m in [0,32768), n in [0,384), k in [0,256)
// Block tile BM=128, BN=128, BK=32. 256 threads = 8 warps (4m x 2n), warp 32x64.
// Register prefetch double-buffer; smem stride 36 (conflict-free frags).
// grid = (256, 3)
// ---------------------------------------------------------------------------
__global__ __launch_bounds__(256) void gemm_kernel(
    const float* __restrict__ Q,
    const float* __restrict__ Woff,
    const float* __restrict__ Wattn,
    const float* __restrict__ boff,
    const float* __restrict__ battn)
{
    __shared__ float As[128][36];
    __shared__ float Bs[128][36];

    const int tid  = threadIdx.x;
    const int m0   = blockIdx.x * 128;
    const int n0   = blockIdx.y * 128;
    const int warp = tid >> 5, lane = tid & 31;
    const int wm   = (warp & 3) * 32;   // warp row in tile
    const int wn   = (warp >> 2) * 64;  // warp col in tile
    const int g    = lane >> 2;         // 0..7
    const int tg   = lane & 3;          // 0..3

    // Per-block B source is uniform: blocks y=0,1 -> Woff rows, y=2 -> Wattn rows
    const float* Bbase = (blockIdx.y == 2) ? Wattn : (Woff + (size_t)n0 * 256);

    // Staging indices: 1024 float4 slots; 4 per thread
    const int sr = tid >> 1;              // unused helper removed below
    (void)sr;

    float acc[2][8][4];
#pragma unroll
    for (int mi = 0; mi < 2; mi++)
#pragma unroll
        for (int ni = 0; ni < 8; ni++)
#pragma unroll
            for (int k = 0; k < 4; k++) acc[mi][ni][k] = 0.f;

    float4 aS[4], bS[4];
    // prologue: load k-tile 0
#pragma unroll
    for (int i = 0; i < 4; i++) {
        int idx = tid + i * 256;
        int r = idx >> 3, c = (idx & 7) * 4;
        aS[i] = *(const float4*)(Q + (size_t)(m0 + r) * 256 + c);
        bS[i] = *(const float4*)(Bbase + (size_t)r * 256 + c);
    }

#pragma unroll
    for (int kt = 0; kt < 8; kt++) {
        if (kt) __syncthreads();
        // store staged registers into smem (float4, stride 36 floats -> 16B aligned)
#pragma unroll
        for (int i = 0; i < 4; i++) {
            int idx = tid + i * 256;
            int r = idx >> 3, c = (idx & 7) * 4;
            *(float4*)(&As[r][c]) = aS[i];
            *(float4*)(&Bs[r][c]) = bS[i];
        }
        __syncthreads();
        // prefetch next k-tile into registers (overlaps with compute below)
        if (kt < 7) {
            int koff = (kt + 1) * 32;
#pragma unroll
            for (int i = 0; i < 4; i++) {
                int idx = tid + i * 256;
                int r = idx >> 3, c = (idx & 7) * 4;
                aS[i] = *(const float4*)(Q + (size_t)(m0 + r) * 256 + koff + c);
                bS[i] = *(const float4*)(Bbase + (size_t)r * 256 + koff + c);
            }
        }
        // compute
#pragma unroll
        for (int kk = 0; kk < 32; kk += 8) {
            unsigned a[2][4];
#pragma unroll
            for (int mi = 0; mi < 2; mi++) {
                int r = wm + mi * 16 + g;
                a[mi][0] = __float_as_uint(As[r][kk + tg]);
                a[mi][1] = __float_as_uint(As[r + 8][kk + tg]);
                a[mi][2] = __float_as_uint(As[r][kk + tg + 4]);
                a[mi][3] = __float_as_uint(As[r + 8][kk + tg + 4]);
            }
#pragma unroll
            for (int ni = 0; ni < 8; ni++) {
                unsigned b0 = __float_as_uint(Bs[wn + ni * 8 + g][kk + tg]);
                unsigned b1 = __float_as_uint(Bs[wn + ni * 8 + g][kk + tg + 4]);
                mma_tf32(acc[0][ni], a[0], b0, b1);
                mma_tf32(acc[1][ni], a[1], b0, b1);
            }
        }
    }

    // Epilogue: add bias, write to scratch
#pragma unroll
    for (int mi = 0; mi < 2; mi++) {
        int row = m0 + wm + mi * 16 + g;
#pragma unroll
        for (int ni = 0; ni < 8; ni++) {
            int col = n0 + wn + ni * 8 + 2 * tg;
            float b0v = (col < 256) ? boff[col] : battn[col - 256];
            float b1v = (col + 1 < 256) ? boff[col + 1] : battn[col + 1 - 256];
            g_scratch[(size_t)row * NOUT + col]           = acc[mi][ni][0] + b0v;
            g_scratch[(size_t)row * NOUT + col + 1]       = acc[mi][ni][1] + b1v;
            g_scratch[(size_t)(row + 8) * NOUT + col]     = acc[mi][ni][2] + b0v;
            g_scratch[(size_t)(row + 8) * NOUT + col + 1] = acc[mi][ni][3] + b1v;
        }
    }
}

// ---------------------------------------------------------------------------
// MSDA kernel: softmax + 16-point bilinear gather + weighted sum.
// Block = 1024 threads = 32 warps, one warp per query; grid (512, 8, 2).
// Lane layout: half = lane>>4 selects x-column (x0 / x1); c2 = lane&15 is the
// channel pair. Lane pt (and pt+16) precompute point pt's scalars; validity is
// folded into tap weights, positions clamped in-bounds and packed 16+16 bits.
// Hot loop per point: 3 SHFL + 2 LDG.64 + 4 FFMA.
// ---------------------------------------------------------------------------
__global__ __launch_bounds__(1024) void msda_kernel(
    const float* __restrict__ value,
    const float* __restrict__ refp,
    float* __restrict__ out)
{
    const int b    = blockIdx.z;
    const int h    = blockIdx.y;
    const int warp = threadIdx.x >> 5;
    const int lane = threadIdx.x & 31;
    const int q    = blockIdx.x * 32 + warp;
    const int qg   = b * NQ + q;

    const float* sc = g_scratch + (size_t)qg * NOUT;

    const int pt   = lane & 15;       // point index (both halves compute it)
    const int half = lane >> 4;       // 0 -> x0 column taps, 1 -> x1 column taps
    const int l    = pt >> 2;
    const int p    = pt & 3;
    const int Wl   = 128 >> l;
    const int start = (l == 0) ? 0 : (l == 1) ? 16384 : (l == 2) ? 20480 : 21504;

    // ---- softmax over the 16 logits (replicated in both 16-lane halves) ----
    float lg = sc[256 + h * 16 + pt];
    float mx = lg;
#pragma unroll
    for (int o = 8; o; o >>= 1)
        mx = fmaxf(mx, __shfl_xor_sync(0xffffffffu, mx, o));
    float e = __expf(lg - mx);
    float s = e;
#pragma unroll
    for (int o = 8; o; o >>= 1)
        s += __shfl_xor_sync(0xffffffffu, s, o);
    float w = e / s;

    // ---- per-point sampling position ----
    float2 of = ((const float2*)(sc + h * 32))[pt];
    float2 rp = ((const float2*)(refp + (size_t)qg * 8))[p];

    float x = rp.x * (float)Wl + of.x - 0.5f;
    float y = rp.y * (float)Wl + of.y - 0.5f;
    float xf = floorf(x), yf = floorf(y);
    float fx = x - xf, fy = y - yf;
    int ix = (int)xf + half;          // this half's x column
    int iy = (int)yf;
    float gxw = half ? fx : (1.f - fx);

    bool vx  = (unsigned)ix       < (unsigned)Wl;
    bool vy0 = (unsigned)iy       < (unsigned)Wl;
    bool vy1 = (unsigned)(iy + 1) < (unsigned)Wl;

    float wA_s = (vx && vy0) ? w * gxw * (1.f - fy) : 0.f;  // tap (x, y)
    float wB_s = (vx && vy1) ? w * gxw * fy         : 0.f;  // tap (x, y+1)

    int ixc = min(max(ix, 0), Wl - 1);
    unsigned posA = (unsigned)(start + min(max(iy,     0), Wl - 1) * Wl + ixc);
    unsigned posB = (unsigned)(start + min(max(iy + 1, 0), Wl - 1) * Wl + ixc);
    unsigned pk_s = posA | (posB << 16);

    // ---- gather loop: lane handles channels 2*c2, 2*c2+1 for its half ----
    const int c2  = pt;
    const int h16 = lane & 16;
    const float* vlane = value + (size_t)b * TOTV * 256 + h * 32 + 2 * c2;

    float acc0 = 0.f, acc1 = 0.f;
#pragma unroll
    for (int i = 0; i < 16; i++) {
        unsigned pk = __shfl_sync(0xffffffffu, pk_s, i | h16);
        float wA    = __shfl_sync(0xffffffffu, wA_s, i | h16);
        float wB    = __shfl_sync(0xffffffffu, wB_s, i | h16);
        float2 vA = __ldg((const float2*)(vlane + ((pk & 0xFFFFu) << 8)));
        float2 vB = __ldg((const float2*)(vlane + ((pk >> 16) << 8)));
        acc0 += wA * vA.x + wB * vB.x;
        acc1 += wA * vA.y + wB * vB.y;
    }
    // combine x0-column (half 0) and x1-column (half 1) partial sums
    acc0 += __shfl_xor_sync(0xffffffffu, acc0, 16);
    acc1 += __shfl_xor_sync(0xffffffffu, acc1, 16);

    // ---- smem transpose for coalesced [b, C, q] stores ----
    __shared__ float sm[32][33];
    if (half == 0) {
        sm[2 * c2][warp]     = acc0;
        sm[2 * c2 + 1][warp] = acc1;
    }
    __syncthreads();
    out[((size_t)(b * 256 + h * 32 + warp)) * NQ + blockIdx.x * 32 + lane] =
        sm[warp][lane];
}

// ---------------------------------------------------------------------------
// Launch
// ---------------------------------------------------------------------------
extern "C" void kernel_launch(void* const* d_in, const int* in_sizes, int n_in,
                              void* d_out, int out_size) {
    const float* query = (const float*)d_in[0];
    const float* value = (const float*)d_in[1];
    const float* refp  = (const float*)d_in[2];
    const float* Woff  = (const float*)d_in[3];
    const float* boff  = (const float*)d_in[4];
    const float* Wattn = (const float*)d_in[5];
    const float* battn = (const float*)d_in[6];
    float* out = (float*)d_out;

    dim3 ggrid(M_TOT / 128, 3);                  // (256, 3)
    gemm_kernel<<<ggrid, 256>>>(query, Woff, Wattn, boff, battn);

    dim3 mgrid(NQ / 32, NH, BS);                 // (512, 8, 2)
    msda_kernel<<<mgrid, 1024>>>(value, refp, out);
}